// round 4
// baseline (speedup 1.0000x reference)
#include <cuda_runtime.h>

// Problem constants
#define BB   2
#define LL   2048
#define DM   2048
#define NH   32
#define NKV  8
#define HD   64
#define MTOT (BB*LL)      // 4096 rows (b*l)
#define KVW  (NKV*HD)     // 512
#define QKVN (DM + 2*KVW) // 3072

// Scratch (packed q/k/v slices + attention output in (b,l,(g h d)) layout)
__device__ __align__(256) float g_q[(size_t)MTOT*DM];
__device__ __align__(256) float g_k[(size_t)MTOT*KVW];
__device__ __align__(256) float g_v[(size_t)MTOT*KVW];
__device__ __align__(256) float g_o[(size_t)MTOT*DM];

// ---------------------------------------------------------------------------
// Packed fp32x2 helpers (sm_103a FFMA2 — ptxas never auto-generates these;
// numerics are two independent .rn fp32 FMAs, identical to scalar FFMA).
// ---------------------------------------------------------------------------
typedef unsigned long long u64;

__device__ __forceinline__ u64 pk2(float lo, float hi) {
    u64 r; asm("mov.b64 %0, {%1, %2};" : "=l"(r) : "f"(lo), "f"(hi)); return r;
}
__device__ __forceinline__ u64 dup2(float v) { return pk2(v, v); }
__device__ __forceinline__ void fma2(u64& d, u64 a, u64 b) {
    asm("fma.rn.f32x2 %0, %1, %2, %0;" : "+l"(d) : "l"(a), "l"(b));
}
__device__ __forceinline__ void mul2(u64& d, u64 a) {
    asm("mul.rn.f32x2 %0, %0, %1;" : "+l"(d) : "l"(a));
}
__device__ __forceinline__ float2 up2(u64 v) {
    float2 f; asm("mov.b64 {%0, %1}, %2;" : "=f"(f.x), "=f"(f.y) : "l"(v)); return f;
}

// ---------------------------------------------------------------------------
// 128x128x8 fp32 GEMM, 256 threads, 8x8 per-thread microtile via FFMA2,
// double-buffered shared memory (1 barrier per k-tile, global loads
// overlapped with compute).
// SPLIT=1: epilogue routes columns into packed g_q / g_k / g_v.
// SPLIT=0: plain C = A @ B.
// All dims are multiples of the tile sizes for this problem (no edge guards).
// ---------------------------------------------------------------------------
template<int SPLIT>
__global__ __launch_bounds__(256)
void sgemm128(const float* __restrict__ A, const float* __restrict__ Bm,
              float* __restrict__ C, int M, int N, int K)
{
    __shared__ float As[2][8][128];
    __shared__ float Bs[2][8][128];   // rows 512B-aligned -> packed loads ok

    const int t  = threadIdx.x;
    const int m0 = blockIdx.y * 128;
    const int n0 = blockIdx.x * 128;

    const int arow = t >> 1, acol = (t & 1) << 2;   // A tile: 128 rows x 8 k
    const int brow = t >> 5, bcol = (t & 31) << 2;  // B tile: 8 k x 128 cols
    const int tx = t & 15, ty = t >> 4;

    u64 acc2[8][4];               // 8 rows x 4 col-pairs (cols tx*4.., 64+tx*4..)
#pragma unroll
    for (int i = 0; i < 8; i++)
#pragma unroll
        for (int j = 0; j < 4; j++) acc2[i][j] = 0ull;

    const float* Aptr = A  + (size_t)(m0 + arow) * K + acol;
    const float* Bptr = Bm + (size_t)brow * N + n0 + bcol;

    const int NT = K / 8;

    // prologue: load tile 0 into buffer 0
    float4 av = *(const float4*)(Aptr);
    float4 bv = *(const float4*)(Bptr);
    As[0][acol + 0][arow] = av.x;
    As[0][acol + 1][arow] = av.y;
    As[0][acol + 2][arow] = av.z;
    As[0][acol + 3][arow] = av.w;
    *(float4*)&Bs[0][brow][bcol] = bv;
    __syncthreads();

    int buf = 0;
    for (int tile = 0; tile < NT; tile++) {
        // prefetch next tile from global (overlaps with compute below)
        if (tile + 1 < NT) {
            const int k0 = (tile + 1) * 8;
            av = *(const float4*)(Aptr + k0);
            bv = *(const float4*)(Bptr + (size_t)k0 * N);
        }
#pragma unroll
        for (int k = 0; k < 8; k++) {
            float a[8];
            *(float4*)(a)     = *(const float4*)&As[buf][k][ty * 4];
            *(float4*)(a + 4) = *(const float4*)&As[buf][k][64 + ty * 4];
            ulonglong2 bl0 = *(const ulonglong2*)&Bs[buf][k][tx * 4];
            ulonglong2 bl1 = *(const ulonglong2*)&Bs[buf][k][64 + tx * 4];
            u64 b2[4] = { bl0.x, bl0.y, bl1.x, bl1.y };
#pragma unroll
            for (int i = 0; i < 8; i++) {
                u64 ad = dup2(a[i]);
#pragma unroll
                for (int j = 0; j < 4; j++) fma2(acc2[i][j], ad, b2[j]);
            }
        }
        if (tile + 1 < NT) {
            const int nb = buf ^ 1;
            As[nb][acol + 0][arow] = av.x;
            As[nb][acol + 1][arow] = av.y;
            As[nb][acol + 2][arow] = av.z;
            As[nb][acol + 3][arow] = av.w;
            *(float4*)&Bs[nb][brow][bcol] = bv;
            __syncthreads();
            buf = nb;
        }
    }

#pragma unroll
    for (int i = 0; i < 8; i++) {
        int row = m0 + ((i < 4) ? (ty * 4 + i) : (64 + ty * 4 + i - 4));
        float2 p0 = up2(acc2[i][0]), p1 = up2(acc2[i][1]);
        float2 p2 = up2(acc2[i][2]), p3 = up2(acc2[i][3]);
        float4 v0 = make_float4(p0.x, p0.y, p1.x, p1.y);
        float4 v1 = make_float4(p2.x, p2.y, p3.x, p3.y);
        if (SPLIT == 0) {
            *(float4*)&C[(size_t)row * N + n0 + tx * 4]      = v0;
            *(float4*)&C[(size_t)row * N + n0 + 64 + tx * 4] = v1;
        } else {
            // Whole 128-wide column block lands in exactly one of q/k/v
            // (slice boundaries 2048, 2560 are multiples of 128).
            float* dst; int ldd, cb;
            if (n0 < NH * HD)              { dst = g_q; ldd = DM;  cb = n0; }
            else if (n0 < (NH+NKV) * HD)   { dst = g_k; ldd = KVW; cb = n0 - NH*HD; }
            else                           { dst = g_v; ldd = KVW; cb = n0 - (NH+NKV)*HD; }
            *(float4*)&dst[(size_t)row * ldd + cb + tx * 4]      = v0;
            *(float4*)&dst[(size_t)row * ldd + cb + 64 + tx * 4] = v1;
        }
    }
}

// ---------------------------------------------------------------------------
// Flash attention, fp32 with FFMA2 inner products.
// BQ=128 query rows, BK=64 key rows, HD=64. 256 threads as 16x16 grid; each
// thread owns an 8x4 S-tile (rows {ty*4+i, 64+ty*4+i}, cols tx*4..tx*4+3).
// Row statistics reduced across the 16 tx lanes via shfl.
// Vs uses its own 16B-aligned row stride (VLD=68) so the P.V loop reads the
// packed V operand with one conflict-free LDS.128 per key row.
// Causal mask == reference's additive -1e9 mask (exp underflows to exactly 0).
// ---------------------------------------------------------------------------
#define AQ 128
#define AK 64
#define QLD 65  // padded row stride for Qs/Ks/Ps (scalar access patterns)
#define VLD 68  // padded row stride for Vs (16B-aligned -> vector loads)

__global__ __launch_bounds__(256)
void attn_kernel()
{
    extern __shared__ float smf[];
    float* Qs = smf;                 // [AQ][QLD]
    float* Ks = Qs + AQ * QLD;       // [AK][QLD]
    float* Vs = Ks + AK * QLD;       // [AK][VLD]  (16B-aligned rows)
    float* Ps = Vs + AK * VLD;       // [AQ][QLD]

    const int t  = threadIdx.x;
    const int tx = t & 15, ty = t >> 4;
    const int qb = (int)gridDim.x - 1 - (int)blockIdx.x;  // big blocks first
    const int bH = blockIdx.y;
    const int bb = bH >> 5;       // batch
    const int H  = bH & 31;       // fused head index g*8+h
    const int hk = H & 7;         // kv head
    const int qg0 = qb * AQ;

    const float* Qg = g_q + (size_t)bb * LL * DM  + (size_t)H  * LL * HD;
    const float* Kg = g_k + (size_t)bb * LL * KVW + (size_t)hk * LL * HD;
    const float* Vg = g_v + (size_t)bb * LL * KVW + (size_t)hk * LL * HD;

    // Load Q tile (128x64) into padded smem
#pragma unroll
    for (int s = 0; s < (AQ * HD / 4) / 256; s++) {
        int idx = t + 256 * s;              // 0..2047 float4s
        int row = idx >> 4, d4 = (idx & 15) << 2;
        float4 v = *(const float4*)&Qg[(size_t)(qg0 + row) * HD + d4];
        Qs[row * QLD + d4 + 0] = v.x;
        Qs[row * QLD + d4 + 1] = v.y;
        Qs[row * QLD + d4 + 2] = v.z;
        Qs[row * QLD + d4 + 3] = v.w;
    }

    int rl[8];
#pragma unroll
    for (int i = 0; i < 8; i++) rl[i] = (i < 4) ? (ty * 4 + i) : (64 + ty * 4 + i - 4);

    float m[8], l[8];
    u64 o2[8][2];                   // packed output accumulators (4 cols/row)
#pragma unroll
    for (int i = 0; i < 8; i++) {
        m[i] = -1e30f; l[i] = 0.f;
        o2[i][0] = 0ull; o2[i][1] = 0ull;
    }

    const int nkb = 2 * qb + 2;   // causal: keys up to qg0+127
    for (int kb = 0; kb < nkb; kb++) {
        const int j0 = kb * AK;
        __syncthreads();  // previous iter's reads done (also publishes Q on kb=0)
#pragma unroll
        for (int s = 0; s < (AK * HD / 4) / 256; s++) {
            int idx = t + 256 * s;          // 0..1023 float4s
            int j = idx >> 4, d4 = (idx & 15) << 2;
            float4 kv = *(const float4*)&Kg[(size_t)(j0 + j) * HD + d4];
            Ks[j * QLD + d4 + 0] = kv.x; Ks[j * QLD + d4 + 1] = kv.y;
            Ks[j * QLD + d4 + 2] = kv.z; Ks[j * QLD + d4 + 3] = kv.w;
            float4 vv = *(const float4*)&Vg[(size_t)(j0 + j) * HD + d4];
            *(float4*)&Vs[j * VLD + d4] = vv;   // 16B-aligned row stride
        }
        __syncthreads();

        // S = Q K^T  (8 rows x 2 col-pairs per thread, FFMA2)
        u64 s2[8][2];
#pragma unroll
        for (int i = 0; i < 8; i++) { s2[i][0] = 0ull; s2[i][1] = 0ull; }

#pragma unroll 4
        for (int d = 0; d < HD; d++) {
            float a[8];
#pragma unroll
            for (int i = 0; i < 8; i++) a[i] = Qs[rl[i] * QLD + d];
            u64 bb0 = pk2(Ks[(tx*4 + 0) * QLD + d], Ks[(tx*4 + 1) * QLD + d]);
            u64 bb1 = pk2(Ks[(tx*4 + 2) * QLD + d], Ks[(tx*4 + 3) * QLD + d]);
#pragma unroll
            for (int i = 0; i < 8; i++) {
                u64 ad = dup2(a[i]);
                fma2(s2[i][0], ad, bb0);
                fma2(s2[i][1], ad, bb1);
            }
        }

        const bool needmask = (j0 + AK - 1 > qg0);

        // online softmax per row
#pragma unroll
        for (int i = 0; i < 8; i++) {
            const int qglob = qg0 + rl[i];
            float s8[4];
            float2 u0 = up2(s2[i][0]), u1 = up2(s2[i][1]);
            s8[0] = u0.x; s8[1] = u0.y; s8[2] = u1.x; s8[3] = u1.y;
            float mx = -1e30f;
#pragma unroll
            for (int j = 0; j < 4; j++) {
                float sv = s8[j] * 0.125f;  // HEAD_DIM^-0.5
                if (needmask && (j0 + tx * 4 + j > qglob)) sv = -1e30f;
                s8[j] = sv;
                mx = fmaxf(mx, sv);
            }
            mx = fmaxf(mx, __shfl_xor_sync(0xffffffffu, mx, 1));
            mx = fmaxf(mx, __shfl_xor_sync(0xffffffffu, mx, 2));
            mx = fmaxf(mx, __shfl_xor_sync(0xffffffffu, mx, 4));
            mx = fmaxf(mx, __shfl_xor_sync(0xffffffffu, mx, 8));
            float mnew  = fmaxf(m[i], mx);
            float alpha = __expf(m[i] - mnew);
            m[i] = mnew;
            float rs = 0.f;
#pragma unroll
            for (int j = 0; j < 4; j++) {
                float p = __expf(s8[j] - mnew);
                s8[j] = p;
                rs += p;
            }
            rs += __shfl_xor_sync(0xffffffffu, rs, 1);
            rs += __shfl_xor_sync(0xffffffffu, rs, 2);
            rs += __shfl_xor_sync(0xffffffffu, rs, 4);
            rs += __shfl_xor_sync(0xffffffffu, rs, 8);
            l[i] = l[i] * alpha + rs;
            u64 a2 = dup2(alpha);
            mul2(o2[i][0], a2);
            mul2(o2[i][1], a2);
            Ps[rl[i] * QLD + tx * 4 + 0] = s8[0];
            Ps[rl[i] * QLD + tx * 4 + 1] = s8[1];
            Ps[rl[i] * QLD + tx * 4 + 2] = s8[2];
            Ps[rl[i] * QLD + tx * 4 + 3] = s8[3];
        }
        __syncthreads();

        // O += P V  (8 rows x 2 col-pairs per thread, FFMA2; V loads packed)
#pragma unroll 4
        for (int j = 0; j < AK; j++) {
            float pp[8];
#pragma unroll
            for (int i = 0; i < 8; i++) pp[i] = Ps[rl[i] * QLD + j];
            ulonglong2 vv = *(const ulonglong2*)&Vs[j * VLD + tx * 4];
#pragma unroll
            for (int i = 0; i < 8; i++) {
                u64 pd = dup2(pp[i]);
                fma2(o2[i][0], pd, vv.x);
                fma2(o2[i][1], pd, vv.y);
            }
        }
    }

    // write O in (b, l, (g h d)) layout: column H*64 + d
#pragma unroll
    for (int i = 0; i < 8; i++) {
        float inv = 1.f / l[i];
        float2 q0 = up2(o2[i][0]), q1 = up2(o2[i][1]);
        float4 v = make_float4(q0.x * inv, q0.y * inv, q1.x * inv, q1.y * inv);
        int row = qg0 + rl[i];
        *(float4*)&g_o[(size_t)(bb * LL + row) * DM + H * HD + tx * 4] = v;
    }
}

// ---------------------------------------------------------------------------
extern "C" void kernel_launch(void* const* d_in, const int* in_sizes, int n_in,
                              void* d_out, int out_size)
{
    (void)in_sizes; (void)n_in; (void)out_size;
    const float* x    = (const float*)d_in[0];
    // d_in[1] is the additive causal mask: exactly reproduced by in-kernel
    // causal masking (exp of -1e9-shifted scores underflows to 0 in fp32).
    const float* Wqkv = (const float*)d_in[2];
    const float* Wout = (const float*)d_in[3];
    float* out = (float*)d_out;

    float* op = nullptr;
    cudaGetSymbolAddress((void**)&op, g_o);

    // 1) QKV projection, split into packed q/k/v
    sgemm128<1><<<dim3(QKVN / 128, MTOT / 128), 256>>>(x, Wqkv, nullptr,
                                                       MTOT, QKVN, DM);

    // 2) attention
    const int smbytes = (AQ * QLD + AK * QLD + AK * VLD + AQ * QLD) * (int)sizeof(float);
    cudaFuncSetAttribute(attn_kernel,
                         cudaFuncAttributeMaxDynamicSharedMemorySize, smbytes);
    attn_kernel<<<dim3(LL / AQ, BB * NH), 256, smbytes>>>();

    // 3) output projection
    sgemm128<0><<<dim3(DM / 128, MTOT / 128), 256>>>(op, Wout, out,
                                                     MTOT, DM, DM);
}

// round 6
// speedup vs baseline: 1.3464x; 1.3464x over previous
#include <cuda_runtime.h>
#include <cuda_bf16.h>
#include <cstdint>

// Problem constants
#define BB   2
#define LL   2048
#define DM   2048
#define NH   32
#define NKV  8
#define HD   64
#define MTOT (BB*LL)      // 4096 rows (b*l)
#define KVW  (NKV*HD)     // 512
#define QKVN (DM + 2*KVW) // 3072

// fp32 scratch consumed by attention
__device__ __align__(256) float g_q[(size_t)MTOT*DM];
__device__ __align__(256) float g_k[(size_t)MTOT*KVW];
__device__ __align__(256) float g_v[(size_t)MTOT*KVW];
// bf16 hi/lo split operands for the tensor-core GEMMs
__device__ __align__(256) __nv_bfloat16 x_hi[(size_t)MTOT*DM];
__device__ __align__(256) __nv_bfloat16 x_lo[(size_t)MTOT*DM];
__device__ __align__(256) __nv_bfloat16 wq_hi[(size_t)QKVN*DM];  // [N=3072][K=2048] (transposed)
__device__ __align__(256) __nv_bfloat16 wq_lo[(size_t)QKVN*DM];
__device__ __align__(256) __nv_bfloat16 wo_hi[(size_t)DM*DM];    // [N=2048][K=2048]
__device__ __align__(256) __nv_bfloat16 wo_lo[(size_t)DM*DM];
__device__ __align__(256) __nv_bfloat16 o_hi[(size_t)MTOT*DM];   // attention out, split
__device__ __align__(256) __nv_bfloat16 o_lo[(size_t)MTOT*DM];

// ---------------------------------------------------------------------------
// Helpers
// ---------------------------------------------------------------------------
typedef unsigned long long u64;

__device__ __forceinline__ u64 pk2(float lo, float hi) {
    u64 r; asm("mov.b64 %0, {%1, %2};" : "=l"(r) : "f"(lo), "f"(hi)); return r;
}
__device__ __forceinline__ u64 dup2(float v) { return pk2(v, v); }
__device__ __forceinline__ void fma2(u64& d, u64 a, u64 b) {
    asm("fma.rn.f32x2 %0, %1, %2, %0;" : "+l"(d) : "l"(a), "l"(b));
}
__device__ __forceinline__ void mul2(u64& d, u64 a) {
    asm("mul.rn.f32x2 %0, %0, %1;" : "+l"(d) : "l"(a));
}
__device__ __forceinline__ float2 up2(u64 v) {
    float2 f; asm("mov.b64 {%0, %1}, %2;" : "=f"(f.x), "=f"(f.y) : "l"(v)); return f;
}

__device__ __forceinline__ uint32_t smem_u32(const void* p) {
    uint32_t a;
    asm("{ .reg .u64 t; cvta.to.shared.u64 t, %1; cvt.u32.u64 %0, t; }"
        : "=r"(a) : "l"(p));
    return a;
}

__device__ __forceinline__ void ldm4(uint32_t addr, uint32_t* r) {
    asm volatile("ldmatrix.sync.aligned.m8n8.x4.shared.b16 {%0,%1,%2,%3}, [%4];"
        : "=r"(r[0]), "=r"(r[1]), "=r"(r[2]), "=r"(r[3]) : "r"(addr));
}

// D += A(m16k16) * B(n8k16)^T, bf16 in, fp32 accum
__device__ __forceinline__ void mma16816(float* c, const uint32_t* a,
                                         uint32_t b0, uint32_t b1) {
    asm volatile(
        "mma.sync.aligned.m16n8k16.row.col.f32.bf16.bf16.f32 "
        "{%0,%1,%2,%3}, {%4,%5,%6,%7}, {%8,%9}, {%0,%1,%2,%3};"
        : "+f"(c[0]), "+f"(c[1]), "+f"(c[2]), "+f"(c[3])
        : "r"(a[0]), "r"(a[1]), "r"(a[2]), "r"(a[3]), "r"(b0), "r"(b1));
}

__device__ __forceinline__ void split_hl(float v, unsigned short& h, unsigned short& l) {
    __nv_bfloat16 bh = __float2bfloat16_rn(v);
    h = __bfloat16_as_ushort(bh);
    float r = v - __bfloat162float(bh);
    l = __bfloat16_as_ushort(__float2bfloat16_rn(r));
}

// ---------------------------------------------------------------------------
// Prep kernels (unchanged from R5)
// ---------------------------------------------------------------------------
__global__ __launch_bounds__(256)
void split_x_kernel(const float* __restrict__ x)
{
    size_t i4 = (size_t)blockIdx.x * 256 + threadIdx.x;   // one float4 each
    float4 v = *((const float4*)x + i4);
    unsigned short h0, l0, h1, l1, h2, l2, h3, l3;
    split_hl(v.x, h0, l0); split_hl(v.y, h1, l1);
    split_hl(v.z, h2, l2); split_hl(v.w, h3, l3);
    *(uint2*)&x_hi[i4 * 4] = make_uint2((uint32_t)h0 | ((uint32_t)h1 << 16),
                                        (uint32_t)h2 | ((uint32_t)h3 << 16));
    *(uint2*)&x_lo[i4 * 4] = make_uint2((uint32_t)l0 | ((uint32_t)l1 << 16),
                                        (uint32_t)l2 | ((uint32_t)l3 << 16));
}

// Transpose W[K][N] -> T[N][K] with hi/lo split. block (32,8), 32x32 tiles.
__global__ __launch_bounds__(256)
void wsplit_kernel(const float* __restrict__ W, __nv_bfloat16* __restrict__ Thi,
                   __nv_bfloat16* __restrict__ Tlo, int K, int N)
{
    __shared__ float tile[32][33];
    int n0 = blockIdx.x * 32, k0 = blockIdx.y * 32;
    int tx = threadIdx.x, ty = threadIdx.y;
#pragma unroll
    for (int i = 0; i < 4; i++)
        tile[ty + 8 * i][tx] = W[(size_t)(k0 + ty + 8 * i) * N + n0 + tx];
    __syncthreads();
#pragma unroll
    for (int i = 0; i < 4; i++) {
        int n = n0 + ty + 8 * i, k = k0 + tx;
        unsigned short h, l;
        split_hl(tile[tx][ty + 8 * i], h, l);
        Thi[(size_t)n * K + k] = __ushort_as_bfloat16(h);
        Tlo[(size_t)n * K + k] = __ushort_as_bfloat16(l);
    }
}

// ---------------------------------------------------------------------------
// bf16x3 GEMM on mma.sync (sm_80-class HMMA, compiles under compute_103).
// C[128x128 tile] = A(hi+lo) @ B(hi+lo)^T, fp32 accum, dropping lo*lo.
// A: [M][2048] bf16 K-major.  B: [N][2048] bf16 K-major (pre-transposed).
// 8 warps in 2x4; warp tile 64x32 (4 m-tiles x 4 n-tiles of m16n8k16).
// Smem rows padded to 40 halves (80B): ldmatrix phases conflict-free.
// Register-prefetch double buffering of the 4x(128x32) bf16 chunk tiles.
// ---------------------------------------------------------------------------
#define KS 40            // halves per smem row (80B, 16B-aligned)
#define BK 32
#define NTCH (2048/BK)   // 64 k-chunks

template<int SPLIT>
__global__ __launch_bounds__(256)
void hmma_gemm(const __nv_bfloat16* __restrict__ Ahi, const __nv_bfloat16* __restrict__ Alo,
               const __nv_bfloat16* __restrict__ Bhi, const __nv_bfloat16* __restrict__ Blo,
               float* __restrict__ C, int N)
{
    __shared__ __nv_bfloat16 sm[4][128 * KS];   // Ahi Alo Bhi Blo

    const int t    = threadIdx.x;
    const int lane = t & 31, wid = t >> 5;
    const int wm = wid >> 2, wn = wid & 3;      // 2x4 warp grid
    const int m0 = blockIdx.y * 128;
    const int n0 = blockIdx.x * 128;

    const int lrow = lane & 15, lhalf = lane >> 4;

    uint32_t smb[4];
#pragma unroll
    for (int a = 0; a < 4; a++) smb[a] = smem_u32(sm[a]);

    // ldmatrix byte offsets (within one array) for this lane
    uint32_t aOff[4], bOff[2];
#pragma unroll
    for (int mt = 0; mt < 4; mt++)
        aOff[mt] = (uint32_t)(wm * 64 + mt * 16 + lrow) * (KS * 2) + lhalf * 16;
#pragma unroll
    for (int np = 0; np < 2; np++)
        bOff[np] = (uint32_t)(wn * 32 + np * 16 + lrow) * (KS * 2) + lhalf * 16;

    // global load mapping: thread loads rows {t>>2, 64+(t>>2)}, 16B chunk q=t&3
    const int grow = t >> 2, gq = t & 3;
    const __nv_bfloat16* srcs[4] = {
        Ahi + (size_t)m0 * 2048, Alo + (size_t)m0 * 2048,
        Bhi + (size_t)n0 * 2048, Blo + (size_t)n0 * 2048 };

    float acc[4][4][4];
#pragma unroll
    for (int mt = 0; mt < 4; mt++)
#pragma unroll
        for (int nt = 0; nt < 4; nt++)
#pragma unroll
            for (int r = 0; r < 4; r++) acc[mt][nt][r] = 0.f;

    uint4 pf[4][2];

    // prologue: chunk 0
#pragma unroll
    for (int a = 0; a < 4; a++) {
        pf[a][0] = *(const uint4*)(srcs[a] + (size_t)grow * 2048 + gq * 8);
        pf[a][1] = *(const uint4*)(srcs[a] + (size_t)(grow + 64) * 2048 + gq * 8);
    }
#pragma unroll
    for (int a = 0; a < 4; a++) {
        *(uint4*)&sm[a][grow * KS + gq * 8]        = pf[a][0];
        *(uint4*)&sm[a][(grow + 64) * KS + gq * 8] = pf[a][1];
    }
    __syncthreads();

    for (int c = 0; c < NTCH; c++) {
        // prefetch chunk c+1 into regs
        if (c + 1 < NTCH) {
            const int k0 = (c + 1) * BK;
#pragma unroll
            for (int a = 0; a < 4; a++) {
                pf[a][0] = *(const uint4*)(srcs[a] + (size_t)grow * 2048 + k0 + gq * 8);
                pf[a][1] = *(const uint4*)(srcs[a] + (size_t)(grow + 64) * 2048 + k0 + gq * 8);
            }
        }

        // compute chunk c
#pragma unroll
        for (int ks = 0; ks < 2; ks++) {
            const uint32_t kb = ks * 32;   // 16 halves = 32 bytes
            uint32_t Af[4][4], Bf[2][4], Cf[2][4];
#pragma unroll
            for (int mt = 0; mt < 4; mt++) ldm4(smb[0] + aOff[mt] + kb, Af[mt]);
#pragma unroll
            for (int np = 0; np < 2; np++) ldm4(smb[2] + bOff[np] + kb, Bf[np]);
            // hh
#pragma unroll
            for (int mt = 0; mt < 4; mt++)
#pragma unroll
                for (int nt = 0; nt < 4; nt++)
                    mma16816(acc[mt][nt], Af[mt],
                             Bf[nt >> 1][nt & 1], Bf[nt >> 1][2 + (nt & 1)]);
            // h * Blo
#pragma unroll
            for (int np = 0; np < 2; np++) ldm4(smb[3] + bOff[np] + kb, Cf[np]);
#pragma unroll
            for (int mt = 0; mt < 4; mt++)
#pragma unroll
                for (int nt = 0; nt < 4; nt++)
                    mma16816(acc[mt][nt], Af[mt],
                             Cf[nt >> 1][nt & 1], Cf[nt >> 1][2 + (nt & 1)]);
            // Alo * h  (reuse Af regs)
#pragma unroll
            for (int mt = 0; mt < 4; mt++) ldm4(smb[1] + aOff[mt] + kb, Af[mt]);
#pragma unroll
            for (int mt = 0; mt < 4; mt++)
#pragma unroll
                for (int nt = 0; nt < 4; nt++)
                    mma16816(acc[mt][nt], Af[mt],
                             Bf[nt >> 1][nt & 1], Bf[nt >> 1][2 + (nt & 1)]);
        }

        if (c + 1 < NTCH) {
            __syncthreads();
#pragma unroll
            for (int a = 0; a < 4; a++) {
                *(uint4*)&sm[a][grow * KS + gq * 8]        = pf[a][0];
                *(uint4*)&sm[a][(grow + 64) * KS + gq * 8] = pf[a][1];
            }
            __syncthreads();
        }
    }

    // epilogue: c-frag m16n8 layout: c0,c1 -> row lane>>2, cols (lane&3)*2..+1;
    // c2,c3 -> row +8.  Route whole 128-col block per SPLIT.
    float* dst; int ldd, cb;
    if (SPLIT == 0)               { dst = C;   ldd = N;   cb = n0; }
    else if (n0 < NH * HD)        { dst = g_q; ldd = DM;  cb = n0; }
    else if (n0 < (NH+NKV) * HD)  { dst = g_k; ldd = KVW; cb = n0 - NH*HD; }
    else                          { dst = g_v; ldd = KVW; cb = n0 - (NH+NKV)*HD; }

    const int erow = lane >> 2, ecol = (lane & 3) * 2;
#pragma unroll
    for (int mt = 0; mt < 4; mt++) {
        const int r0 = m0 + wm * 64 + mt * 16 + erow;
#pragma unroll
        for (int nt = 0; nt < 4; nt++) {
            const int cc = cb + wn * 32 + nt * 8 + ecol;
            *(float2*)&dst[(size_t)r0 * ldd + cc]       =
                make_float2(acc[mt][nt][0], acc[mt][nt][1]);
            *(float2*)&dst[(size_t)(r0 + 8) * ldd + cc] =
                make_float2(acc[mt][nt][2], acc[mt][nt][3]);
        }
    }
}

// ---------------------------------------------------------------------------
// Flash attention, fp32 FFMA2 (proven in R4; hi/lo bf16 epilogue).
// ---------------------------------------------------------------------------
#define AQ 128
#define AK 64
#define QLD 65
#define VLD 68

__global__ __launch_bounds__(256)
void attn_kernel()
{
    extern __shared__ float smf[];
    float* Qs = smf;
    float* Ks = Qs + AQ * QLD;
    float* Vs = Ks + AK * QLD;
    float* Ps = Vs + AK * VLD;

    const int t  = threadIdx.x;
    const int tx = t & 15, ty = t >> 4;
    const int qb = (int)gridDim.x - 1 - (int)blockIdx.x;
    const int bH = blockIdx.y;
    const int bb = bH >> 5;
    const int H  = bH & 31;
    const int hk = H & 7;
    const int qg0 = qb * AQ;

    const float* Qg = g_q + (size_t)bb * LL * DM  + (size_t)H  * LL * HD;
    const float* Kg = g_k + (size_t)bb * LL * KVW + (size_t)hk * LL * HD;
    const float* Vg = g_v + (size_t)bb * LL * KVW + (size_t)hk * LL * HD;

#pragma unroll
    for (int s = 0; s < (AQ * HD / 4) / 256; s++) {
        int idx = t + 256 * s;
        int row = idx >> 4, d4 = (idx & 15) << 2;
        float4 v = *(const float4*)&Qg[(size_t)(qg0 + row) * HD + d4];
        Qs[row * QLD + d4 + 0] = v.x;
        Qs[row * QLD + d4 + 1] = v.y;
        Qs[row * QLD + d4 + 2] = v.z;
        Qs[row * QLD + d4 + 3] = v.w;
    }

    int rl[8];
#pragma unroll
    for (int i = 0; i < 8; i++) rl[i] = (i < 4) ? (ty * 4 + i) : (64 + ty * 4 + i - 4);

    float m[8], l[8];
    u64 o2[8][2];
#pragma unroll
    for (int i = 0; i < 8; i++) {
        m[i] = -1e30f; l[i] = 0.f;
        o2[i][0] = 0ull; o2[i][1] = 0ull;
    }

    const int nkb = 2 * qb + 2;
    for (int kb = 0; kb < nkb; kb++) {
        const int j0 = kb * AK;
        __syncthreads();
#pragma unroll
        for (int s = 0; s < (AK * HD / 4) / 256; s++) {
            int idx = t + 256 * s;
            int j = idx >> 4, d4 = (idx & 15) << 2;
            float4 kv = *(const float4*)&Kg[(size_t)(j0 + j) * HD + d4];
            Ks[j * QLD + d4 + 0] = kv.x; Ks[j * QLD + d4 + 1] = kv.y;
            Ks[j * QLD + d4 + 2] = kv.z; Ks[j * QLD + d4 + 3] = kv.w;
            float4 vv = *(const float4*)&Vg[(size_t)(j0 + j) * HD + d4];
            *(float4*)&Vs[j * VLD + d4] = vv;
        }
        __syncthreads();

        u64 s2[8][2];
#pragma unroll
        for (int i = 0; i < 8; i++) { s2[i][0] = 0ull; s2[i][1] = 0ull; }

#pragma unroll 4
        for (int d = 0; d < HD; d++) {
            float a[8];
#pragma unroll
            for (int i = 0; i < 8; i++) a[i] = Qs[rl[i] * QLD + d];
            u64 bb0 = pk2(Ks[(tx*4 + 0) * QLD + d], Ks[(tx*4 + 1) * QLD + d]);
            u64 bb1 = pk2(Ks[(tx*4 + 2) * QLD + d], Ks[(tx*4 + 3) * QLD + d]);
#pragma unroll
            for (int i = 0; i < 8; i++) {
                u64 ad = dup2(a[i]);
                fma2(s2[i][0], ad, bb0);
                fma2(s2[i][1], ad, bb1);
            }
        }

        const bool needmask = (j0 + AK - 1 > qg0);
#pragma unroll
        for (int i = 0; i < 8; i++) {
            const int qglob = qg0 + rl[i];
            float s8[4];
            float2 u0 = up2(s2[i][0]), u1 = up2(s2[i][1]);
            s8[0] = u0.x; s8[1] = u0.y; s8[2] = u1.x; s8[3] = u1.y;
            float mx = -1e30f;
#pragma unroll
            for (int j = 0; j < 4; j++) {
                float sv = s8[j] * 0.125f;
                if (needmask && (j0 + tx * 4 + j > qglob)) sv = -1e30f;
                s8[j] = sv;
                mx = fmaxf(mx, sv);
            }
            mx = fmaxf(mx, __shfl_xor_sync(0xffffffffu, mx, 1));
            mx = fmaxf(mx, __shfl_xor_sync(0xffffffffu, mx, 2));
            mx = fmaxf(mx, __shfl_xor_sync(0xffffffffu, mx, 4));
            mx = fmaxf(mx, __shfl_xor_sync(0xffffffffu, mx, 8));
            float mnew  = fmaxf(m[i], mx);
            float alpha = __expf(m[i] - mnew);
            m[i] = mnew;
            float rs = 0.f;
#pragma unroll
            for (int j = 0; j < 4; j++) {
                float p = __expf(s8[j] - mnew);
                s8[j] = p;
                rs += p;
            }
            rs += __shfl_xor_sync(0xffffffffu, rs, 1);
            rs += __shfl_xor_sync(0xffffffffu, rs, 2);
            rs += __shfl_xor_sync(0xffffffffu, rs, 4);
            rs += __shfl_xor_sync(0xffffffffu, rs, 8);
            l[i] = l[i] * alpha + rs;
            u64 a2 = dup2(alpha);
            mul2(o2[i][0], a2);
            mul2(o2[i][1], a2);
            Ps[rl[i] * QLD + tx * 4 + 0] = s8[0];
            Ps[rl[i] * QLD + tx * 4 + 1] = s8[1];
            Ps[rl[i] * QLD + tx * 4 + 2] = s8[2];
            Ps[rl[i] * QLD + tx * 4 + 3] = s8[3];
        }
        __syncthreads();

#pragma unroll 4
        for (int j = 0; j < AK; j++) {
            float pp[8];
#pragma unroll
            for (int i = 0; i < 8; i++) pp[i] = Ps[rl[i] * QLD + j];
            ulonglong2 vv = *(const ulonglong2*)&Vs[j * VLD + tx * 4];
#pragma unroll
            for (int i = 0; i < 8; i++) {
                u64 pd = dup2(pp[i]);
                fma2(o2[i][0], pd, vv.x);
                fma2(o2[i][1], pd, vv.y);
            }
        }
    }

    // epilogue: write hi/lo bf16 split of O in (b, l, (g h d)) layout
#pragma unroll
    for (int i = 0; i < 8; i++) {
        float inv = 1.f / l[i];
        float2 q0 = up2(o2[i][0]), q1 = up2(o2[i][1]);
        float v0 = q0.x * inv, v1 = q0.y * inv, v2 = q1.x * inv, v3 = q1.y * inv;
        unsigned short h0,l0,h1,l1,h2,l2,h3,l3;
        split_hl(v0, h0, l0); split_hl(v1, h1, l1);
        split_hl(v2, h2, l2); split_hl(v3, h3, l3);
        int row = qg0 + rl[i];
        size_t base = (size_t)(bb * LL + row) * DM + H * HD + tx * 4;
        *(uint2*)&o_hi[base] = make_uint2((uint32_t)h0 | ((uint32_t)h1 << 16),
                                          (uint32_t)h2 | ((uint32_t)h3 << 16));
        *(uint2*)&o_lo[base] = make_uint2((uint32_t)l0 | ((uint32_t)l1 << 16),
                                          (uint32_t)l2 | ((uint32_t)l3 << 16));
    }
}

// ---------------------------------------------------------------------------
extern "C" void kernel_launch(void* const* d_in, const int* in_sizes, int n_in,
                              void* d_out, int out_size)
{
    (void)in_sizes; (void)n_in; (void)out_size;
    const float* x    = (const float*)d_in[0];
    // d_in[1] (additive causal mask) reproduced exactly by in-kernel masking.
    const float* Wqkv = (const float*)d_in[2];
    const float* Wout = (const float*)d_in[3];
    float* out = (float*)d_out;

    __nv_bfloat16 *p_xh, *p_xl, *p_qh, *p_ql, *p_oh, *p_ol, *p_ohh, *p_oll;
    cudaGetSymbolAddress((void**)&p_xh, x_hi);
    cudaGetSymbolAddress((void**)&p_xl, x_lo);
    cudaGetSymbolAddress((void**)&p_qh, wq_hi);
    cudaGetSymbolAddress((void**)&p_ql, wq_lo);
    cudaGetSymbolAddress((void**)&p_oh, wo_hi);
    cudaGetSymbolAddress((void**)&p_ol, wo_lo);
    cudaGetSymbolAddress((void**)&p_ohh, o_hi);
    cudaGetSymbolAddress((void**)&p_oll, o_lo);

    // 0) prep: split/transposes
    split_x_kernel<<<(MTOT * DM / 4) / 256, 256>>>(x);
    wsplit_kernel<<<dim3(QKVN / 32, DM / 32), dim3(32, 8)>>>(Wqkv, p_qh, p_ql, DM, QKVN);
    wsplit_kernel<<<dim3(DM / 32, DM / 32), dim3(32, 8)>>>(Wout, p_oh, p_ol, DM, DM);

    // 1) QKV projection (tensor cores via mma.sync), split into g_q/g_k/g_v
    hmma_gemm<1><<<dim3(QKVN / 128, MTOT / 128), 256>>>(p_xh, p_xl, p_qh, p_ql,
                                                        nullptr, QKVN);

    // 2) attention (FFMA2)
    const int smbytes = (AQ * QLD + AK * QLD + AK * VLD + AQ * QLD) * (int)sizeof(float);
    cudaFuncSetAttribute(attn_kernel, cudaFuncAttributeMaxDynamicSharedMemorySize, smbytes);
    attn_kernel<<<dim3(LL / AQ, BB * NH), 256, smbytes>>>();

    // 3) output projection (tensor cores via mma.sync)
    hmma_gemm<0><<<dim3(DM / 128, MTOT / 128), 256>>>(p_ohh, p_oll, p_oh, p_ol,
                                                      out, DM);
}

// round 13
// speedup vs baseline: 1.9403x; 1.4411x over previous
#include <cuda_runtime.h>
#include <cuda_bf16.h>
#include <cstdint>

// Problem constants
#define BB   2
#define LL   2048
#define DM   2048
#define NH   32
#define NKV  8
#define HD   64
#define MTOT (BB*LL)      // 4096 rows (b*l)
#define KVW  (NKV*HD)     // 512
#define QKVN (DM + 2*KVW) // 3072

// fp32 scratch consumed by attention
__device__ __align__(256) float g_q[(size_t)MTOT*DM];
__device__ __align__(256) float g_k[(size_t)MTOT*KVW];
__device__ __align__(256) float g_v[(size_t)MTOT*KVW];
// bf16 hi/lo split operands for the tensor-core GEMMs
__device__ __align__(256) __nv_bfloat16 x_hi[(size_t)MTOT*DM];
__device__ __align__(256) __nv_bfloat16 x_lo[(size_t)MTOT*DM];
__device__ __align__(256) __nv_bfloat16 wq_hi[(size_t)QKVN*DM];  // [N=3072][K=2048] (transposed)
__device__ __align__(256) __nv_bfloat16 wq_lo[(size_t)QKVN*DM];
__device__ __align__(256) __nv_bfloat16 wo_hi[(size_t)DM*DM];    // [N=2048][K=2048]
__device__ __align__(256) __nv_bfloat16 wo_lo[(size_t)DM*DM];
__device__ __align__(256) __nv_bfloat16 o_hi[(size_t)MTOT*DM];   // attention out, split
__device__ __align__(256) __nv_bfloat16 o_lo[(size_t)MTOT*DM];

// ---------------------------------------------------------------------------
// Helpers
// ---------------------------------------------------------------------------
__device__ __forceinline__ uint32_t smem_u32(const void* p) {
    uint32_t a;
    asm("{ .reg .u64 t; cvta.to.shared.u64 t, %1; cvt.u32.u64 %0, t; }"
        : "=r"(a) : "l"(p));
    return a;
}

__device__ __forceinline__ void ldm4(uint32_t addr, uint32_t* r) {
    asm volatile("ldmatrix.sync.aligned.m8n8.x4.shared.b16 {%0,%1,%2,%3}, [%4];"
        : "=r"(r[0]), "=r"(r[1]), "=r"(r[2]), "=r"(r[3]) : "r"(addr));
}
__device__ __forceinline__ void ldm4t(uint32_t addr, uint32_t* r) {
    asm volatile("ldmatrix.sync.aligned.m8n8.x4.trans.shared.b16 {%0,%1,%2,%3}, [%4];"
        : "=r"(r[0]), "=r"(r[1]), "=r"(r[2]), "=r"(r[3]) : "r"(addr));
}

// D += A(m16k16) * B(n8k16)^T, bf16 in, fp32 accum
__device__ __forceinline__ void mma16816(float* c, const uint32_t* a,
                                         uint32_t b0, uint32_t b1) {
    asm volatile(
        "mma.sync.aligned.m16n8k16.row.col.f32.bf16.bf16.f32 "
        "{%0,%1,%2,%3}, {%4,%5,%6,%7}, {%8,%9}, {%0,%1,%2,%3};"
        : "+f"(c[0]), "+f"(c[1]), "+f"(c[2]), "+f"(c[3])
        : "r"(a[0]), "r"(a[1]), "r"(a[2]), "r"(a[3]), "r"(b0), "r"(b1));
}

__device__ __forceinline__ void split_hl(float v, unsigned short& h, unsigned short& l) {
    __nv_bfloat16 bh = __float2bfloat16_rn(v);
    h = __bfloat16_as_ushort(bh);
    float r = v - __bfloat162float(bh);
    l = __bfloat16_as_ushort(__float2bfloat16_rn(r));
}

// two floats -> packed bf16x2 hi + residual bf16x2 lo
__device__ __forceinline__ void hl2(float f0, float f1, uint32_t& h, uint32_t& l) {
    unsigned short h0, l0, h1, l1;
    split_hl(f0, h0, l0);
    split_hl(f1, h1, l1);
    h = (uint32_t)h0 | ((uint32_t)h1 << 16);
    l = (uint32_t)l0 | ((uint32_t)l1 << 16);
}

// ---------------------------------------------------------------------------
// Prep kernels
// ---------------------------------------------------------------------------
__global__ __launch_bounds__(256)
void split_x_kernel(const float* __restrict__ x)
{
    size_t i4 = (size_t)blockIdx.x * 256 + threadIdx.x;   // one float4 each
    float4 v = *((const float4*)x + i4);
    unsigned short h0, l0, h1, l1, h2, l2, h3, l3;
    split_hl(v.x, h0, l0); split_hl(v.y, h1, l1);
    split_hl(v.z, h2, l2); split_hl(v.w, h3, l3);
    *(uint2*)&x_hi[i4 * 4] = make_uint2((uint32_t)h0 | ((uint32_t)h1 << 16),
                                        (uint32_t)h2 | ((uint32_t)h3 << 16));
    *(uint2*)&x_lo[i4 * 4] = make_uint2((uint32_t)l0 | ((uint32_t)l1 << 16),
                                        (uint32_t)l2 | ((uint32_t)l3 << 16));
}

// Transpose W[K][N] -> T[N][K] with hi/lo split. block (32,8), 32x32 tiles.
__global__ __launch_bounds__(256)
void wsplit_kernel(const float* __restrict__ W, __nv_bfloat16* __restrict__ Thi,
                   __nv_bfloat16* __restrict__ Tlo, int K, int N)
{
    __shared__ float tile[32][33];
    int n0 = blockIdx.x * 32, k0 = blockIdx.y * 32;
    int tx = threadIdx.x, ty = threadIdx.y;
#pragma unroll
    for (int i = 0; i < 4; i++)
        tile[ty + 8 * i][tx] = W[(size_t)(k0 + ty + 8 * i) * N + n0 + tx];
    __syncthreads();
#pragma unroll
    for (int i = 0; i < 4; i++) {
        int n = n0 + ty + 8 * i, k = k0 + tx;
        unsigned short h, l;
        split_hl(tile[tx][ty + 8 * i], h, l);
        Thi[(size_t)n * K + k] = __ushort_as_bfloat16(h);
        Tlo[(size_t)n * K + k] = __ushort_as_bfloat16(l);
    }
}

// ---------------------------------------------------------------------------
// bf16x3 GEMM on mma.sync (verified in R6).
// ---------------------------------------------------------------------------
#define KS 40            // halves per smem row (80B, 16B-aligned)
#define BK 32
#define NTCH (2048/BK)   // 64 k-chunks

template<int SPLIT>
__global__ __launch_bounds__(256)
void hmma_gemm(const __nv_bfloat16* __restrict__ Ahi, const __nv_bfloat16* __restrict__ Alo,
               const __nv_bfloat16* __restrict__ Bhi, const __nv_bfloat16* __restrict__ Blo,
               float* __restrict__ C, int N)
{
    __shared__ __nv_bfloat16 sm[4][128 * KS];   // Ahi Alo Bhi Blo

    const int t    = threadIdx.x;
    const int lane = t & 31, wid = t >> 5;
    const int wm = wid >> 2, wn = wid & 3;      // 2x4 warp grid
    const int m0 = blockIdx.y * 128;
    const int n0 = blockIdx.x * 128;

    const int lrow = lane & 15, lhalf = lane >> 4;

    uint32_t smb[4];
#pragma unroll
    for (int a = 0; a < 4; a++) smb[a] = smem_u32(sm[a]);

    uint32_t aOff[4], bOff[2];
#pragma unroll
    for (int mt = 0; mt < 4; mt++)
        aOff[mt] = (uint32_t)(wm * 64 + mt * 16 + lrow) * (KS * 2) + lhalf * 16;
#pragma unroll
    for (int np = 0; np < 2; np++)
        bOff[np] = (uint32_t)(wn * 32 + np * 16 + lrow) * (KS * 2) + lhalf * 16;

    const int grow = t >> 2, gq = t & 3;
    const __nv_bfloat16* srcs[4] = {
        Ahi + (size_t)m0 * 2048, Alo + (size_t)m0 * 2048,
        Bhi + (size_t)n0 * 2048, Blo + (size_t)n0 * 2048 };

    float acc[4][4][4];
#pragma unroll
    for (int mt = 0; mt < 4; mt++)
#pragma unroll
        for (int nt = 0; nt < 4; nt++)
#pragma unroll
            for (int r = 0; r < 4; r++) acc[mt][nt][r] = 0.f;

    uint4 pf[4][2];
#pragma unroll
    for (int a = 0; a < 4; a++) {
        pf[a][0] = *(const uint4*)(srcs[a] + (size_t)grow * 2048 + gq * 8);
        pf[a][1] = *(const uint4*)(srcs[a] + (size_t)(grow + 64) * 2048 + gq * 8);
    }
#pragma unroll
    for (int a = 0; a < 4; a++) {
        *(uint4*)&sm[a][grow * KS + gq * 8]        = pf[a][0];
        *(uint4*)&sm[a][(grow + 64) * KS + gq * 8] = pf[a][1];
    }
    __syncthreads();

    for (int c = 0; c < NTCH; c++) {
        if (c + 1 < NTCH) {
            const int k0 = (c + 1) * BK;
#pragma unroll
            for (int a = 0; a < 4; a++) {
                pf[a][0] = *(const uint4*)(srcs[a] + (size_t)grow * 2048 + k0 + gq * 8);
                pf[a][1] = *(const uint4*)(srcs[a] + (size_t)(grow + 64) * 2048 + k0 + gq * 8);
            }
        }
#pragma unroll
        for (int ks = 0; ks < 2; ks++) {
            const uint32_t kb = ks * 32;
            uint32_t Af[4][4], Bf[2][4], Cf[2][4];
#pragma unroll
            for (int mt = 0; mt < 4; mt++) ldm4(smb[0] + aOff[mt] + kb, Af[mt]);
#pragma unroll
            for (int np = 0; np < 2; np++) ldm4(smb[2] + bOff[np] + kb, Bf[np]);
#pragma unroll
            for (int mt = 0; mt < 4; mt++)
#pragma unroll
                for (int nt = 0; nt < 4; nt++)
                    mma16816(acc[mt][nt], Af[mt],
                             Bf[nt >> 1][nt & 1], Bf[nt >> 1][2 + (nt & 1)]);
#pragma unroll
            for (int np = 0; np < 2; np++) ldm4(smb[3] + bOff[np] + kb, Cf[np]);
#pragma unroll
            for (int mt = 0; mt < 4; mt++)
#pragma unroll
                for (int nt = 0; nt < 4; nt++)
                    mma16816(acc[mt][nt], Af[mt],
                             Cf[nt >> 1][nt & 1], Cf[nt >> 1][2 + (nt & 1)]);
#pragma unroll
            for (int mt = 0; mt < 4; mt++) ldm4(smb[1] + aOff[mt] + kb, Af[mt]);
#pragma unroll
            for (int mt = 0; mt < 4; mt++)
#pragma unroll
                for (int nt = 0; nt < 4; nt++)
                    mma16816(acc[mt][nt], Af[mt],
                             Bf[nt >> 1][nt & 1], Bf[nt >> 1][2 + (nt & 1)]);
        }

        if (c + 1 < NTCH) {
            __syncthreads();
#pragma unroll
            for (int a = 0; a < 4; a++) {
                *(uint4*)&sm[a][grow * KS + gq * 8]        = pf[a][0];
                *(uint4*)&sm[a][(grow + 64) * KS + gq * 8] = pf[a][1];
            }
            __syncthreads();
        }
    }

    float* dst; int ldd, cb;
    if (SPLIT == 0)               { dst = C;   ldd = N;   cb = n0; }
    else if (n0 < NH * HD)        { dst = g_q; ldd = DM;  cb = n0; }
    else if (n0 < (NH+NKV) * HD)  { dst = g_k; ldd = KVW; cb = n0 - NH*HD; }
    else                          { dst = g_v; ldd = KVW; cb = n0 - (NH+NKV)*HD; }

    const int erow = lane >> 2, ecol = (lane & 3) * 2;
#pragma unroll
    for (int mt = 0; mt < 4; mt++) {
        const int r0 = m0 + wm * 64 + mt * 16 + erow;
#pragma unroll
        for (int nt = 0; nt < 4; nt++) {
            const int cc = cb + wn * 32 + nt * 8 + ecol;
            *(float2*)&dst[(size_t)r0 * ldd + cc]       =
                make_float2(acc[mt][nt][0], acc[mt][nt][1]);
            *(float2*)&dst[(size_t)(r0 + 8) * ldd + cc] =
                make_float2(acc[mt][nt][2], acc[mt][nt][3]);
        }
    }
}

// ---------------------------------------------------------------------------
// Flash attention on HMMA (bf16 hi/lo x3).  CTA: 128 Q-rows x one (b,H) head.
// 8 warps, each owns 16 Q-rows.  K-blocks of 64 keys.
// S frags feed softmax in registers; P converts to A-frags in registers
// (no smem round-trip).  V loaded as B-frags via ldmatrix.trans.
// ---------------------------------------------------------------------------
#define ATS 72   // bf16 halves per smem row (144B; rows stagger 16B in banks)

__global__ __launch_bounds__(256)
void attn_kernel()
{
    extern __shared__ __nv_bfloat16 smb[];
    __nv_bfloat16* Qh = smb;                 // [128][ATS]
    __nv_bfloat16* Ql = Qh + 128 * ATS;
    __nv_bfloat16* Kh = Ql + 128 * ATS;      // [64][ATS]
    __nv_bfloat16* Kl = Kh + 64 * ATS;
    __nv_bfloat16* Vh = Kl + 64 * ATS;
    __nv_bfloat16* Vl = Vh + 64 * ATS;

    const int t = threadIdx.x;
    const int lane = t & 31, w = t >> 5;
    const int lrow = lane & 15, lhalf = lane >> 4;
    const int erow = lane >> 2, ecol = (lane & 3) * 2;

    const int qb = (int)gridDim.x - 1 - (int)blockIdx.x;  // big blocks first
    const int bH = blockIdx.y;
    const int bb = bH >> 5;
    const int H  = bH & 31;
    const int hk = H & 7;
    const int qg0 = qb * 128;

    const float* Qg = g_q + (size_t)bb * LL * DM  + (size_t)H  * LL * HD;
    const float* Kg = g_k + (size_t)bb * LL * KVW + (size_t)hk * LL * HD;
    const float* Vg = g_v + (size_t)bb * LL * KVW + (size_t)hk * LL * HD;

    // fill Q smem (hi/lo): 128x64 fp32 -> 32 floats per thread
#pragma unroll
    for (int s = 0; s < 8; s++) {
        int idx = t + 256 * s;                 // 0..2047 float4s
        int row = idx >> 4, d4 = (idx & 15) << 2;
        float4 v = *(const float4*)&Qg[(size_t)(qg0 + row) * HD + d4];
        unsigned short h0,l0,h1,l1,h2,l2,h3,l3;
        split_hl(v.x, h0, l0); split_hl(v.y, h1, l1);
        split_hl(v.z, h2, l2); split_hl(v.w, h3, l3);
        *(uint2*)&Qh[row * ATS + d4] = make_uint2((uint32_t)h0 | ((uint32_t)h1 << 16),
                                                  (uint32_t)h2 | ((uint32_t)h3 << 16));
        *(uint2*)&Ql[row * ATS + d4] = make_uint2((uint32_t)l0 | ((uint32_t)l1 << 16),
                                                  (uint32_t)l2 | ((uint32_t)l3 << 16));
    }
    __syncthreads();

    // Q fragments (held in regs for the whole kernel)
    uint32_t Qf[2][4][4];
    {
        uint32_t qoff = (uint32_t)(w * 16 + lrow) * (ATS * 2) + lhalf * 16;
        uint32_t qha = smem_u32(Qh), qla = smem_u32(Ql);
#pragma unroll
        for (int ks = 0; ks < 4; ks++) {
            ldm4(qha + qoff + ks * 32, Qf[0][ks]);
            ldm4(qla + qoff + ks * 32, Qf[1][ks]);
        }
    }

    const uint32_t kha = smem_u32(Kh), kla = smem_u32(Kl);
    const uint32_t vha = smem_u32(Vh), vla = smem_u32(Vl);
    const uint32_t koff = (uint32_t)lrow * (ATS * 2) + lhalf * 16;

    float m0 = -1e30f, m1 = -1e30f, l0 = 0.f, l1 = 0.f;
    float O[8][4];
#pragma unroll
    for (int dt = 0; dt < 8; dt++)
#pragma unroll
        for (int r = 0; r < 4; r++) O[dt][r] = 0.f;

    const int wrow = qg0 + w * 16;          // warp's first row
    const int r0g = wrow + erow;            // this lane's rows
    const int r1g = r0g + 8;
    const int nkb = 2 * qb + 2;

    for (int kb = 0; kb < nkb; kb++) {
        const int j0 = kb * 64;
        __syncthreads();
        // fill K,V hi/lo: 64x64 fp32 each -> 4 float4 per thread per tensor
#pragma unroll
        for (int s = 0; s < 4; s++) {
            int idx = t + 256 * s;
            int row = idx >> 4, d4 = (idx & 15) << 2;
            float4 kv = *(const float4*)&Kg[(size_t)(j0 + row) * HD + d4];
            unsigned short h0,lw0,h1,lw1,h2,lw2,h3,lw3;
            split_hl(kv.x, h0, lw0); split_hl(kv.y, h1, lw1);
            split_hl(kv.z, h2, lw2); split_hl(kv.w, h3, lw3);
            *(uint2*)&Kh[row * ATS + d4] = make_uint2((uint32_t)h0 | ((uint32_t)h1 << 16),
                                                      (uint32_t)h2 | ((uint32_t)h3 << 16));
            *(uint2*)&Kl[row * ATS + d4] = make_uint2((uint32_t)lw0 | ((uint32_t)lw1 << 16),
                                                      (uint32_t)lw2 | ((uint32_t)lw3 << 16));
            float4 vv = *(const float4*)&Vg[(size_t)(j0 + row) * HD + d4];
            split_hl(vv.x, h0, lw0); split_hl(vv.y, h1, lw1);
            split_hl(vv.z, h2, lw2); split_hl(vv.w, h3, lw3);
            *(uint2*)&Vh[row * ATS + d4] = make_uint2((uint32_t)h0 | ((uint32_t)h1 << 16),
                                                      (uint32_t)h2 | ((uint32_t)h3 << 16));
            *(uint2*)&Vl[row * ATS + d4] = make_uint2((uint32_t)lw0 | ((uint32_t)lw1 << 16),
                                                      (uint32_t)lw2 | ((uint32_t)lw3 << 16));
        }
        __syncthreads();

        if (j0 > wrow + 15) continue;       // fully masked for this warp
        const bool pmask = (j0 + 63 > wrow);

        // ---- S = Q K^T (hi*hi + lo*hi + hi*lo) ----
        float Sf[8][4];
#pragma unroll
        for (int nt = 0; nt < 8; nt++)
#pragma unroll
            for (int r = 0; r < 4; r++) Sf[nt][r] = 0.f;

#pragma unroll
        for (int ks = 0; ks < 4; ks++) {
            uint32_t Khf[4][4], Klf[4][4];
#pragma unroll
            for (int g = 0; g < 4; g++) {
                ldm4(kha + (uint32_t)g * 16 * (ATS * 2) + koff + ks * 32, Khf[g]);
                ldm4(kla + (uint32_t)g * 16 * (ATS * 2) + koff + ks * 32, Klf[g]);
            }
#pragma unroll
            for (int nt = 0; nt < 8; nt++) {
                uint32_t b0h = Khf[nt >> 1][nt & 1], b1h = Khf[nt >> 1][2 + (nt & 1)];
                uint32_t b0l = Klf[nt >> 1][nt & 1], b1l = Klf[nt >> 1][2 + (nt & 1)];
                mma16816(Sf[nt], Qf[0][ks], b0h, b1h);
                mma16816(Sf[nt], Qf[1][ks], b0h, b1h);
                mma16816(Sf[nt], Qf[0][ks], b0l, b1l);
            }
        }

        // ---- online softmax in fragment space ----
        float mx0 = -1e30f, mx1 = -1e30f;
#pragma unroll
        for (int nt = 0; nt < 8; nt++) {
#pragma unroll
            for (int v = 0; v < 2; v++) {
                float s = Sf[nt][v] * 0.125f;
                if (pmask && (j0 + nt * 8 + ecol + v > r0g)) s = -1e30f;
                Sf[nt][v] = s;
                mx0 = fmaxf(mx0, s);
            }
#pragma unroll
            for (int v = 2; v < 4; v++) {
                float s = Sf[nt][v] * 0.125f;
                if (pmask && (j0 + nt * 8 + ecol + v - 2 > r1g)) s = -1e30f;
                Sf[nt][v] = s;
                mx1 = fmaxf(mx1, s);
            }
        }
        mx0 = fmaxf(mx0, __shfl_xor_sync(0xffffffffu, mx0, 1));
        mx0 = fmaxf(mx0, __shfl_xor_sync(0xffffffffu, mx0, 2));
        mx1 = fmaxf(mx1, __shfl_xor_sync(0xffffffffu, mx1, 1));
        mx1 = fmaxf(mx1, __shfl_xor_sync(0xffffffffu, mx1, 2));

        float mn0 = fmaxf(m0, mx0), mn1 = fmaxf(m1, mx1);
        float a0 = __expf(m0 - mn0), a1 = __expf(m1 - mn1);
        m0 = mn0; m1 = mn1;
#pragma unroll
        for (int dt = 0; dt < 8; dt++) {
            O[dt][0] *= a0; O[dt][1] *= a0;
            O[dt][2] *= a1; O[dt][3] *= a1;
        }
        float rs0 = 0.f, rs1 = 0.f;
#pragma unroll
        for (int nt = 0; nt < 8; nt++) {
#pragma unroll
            for (int v = 0; v < 2; v++) {
                float p = __expf(Sf[nt][v] - mn0);
                Sf[nt][v] = p; rs0 += p;
            }
#pragma unroll
            for (int v = 2; v < 4; v++) {
                float p = __expf(Sf[nt][v] - mn1);
                Sf[nt][v] = p; rs1 += p;
            }
        }
        rs0 += __shfl_xor_sync(0xffffffffu, rs0, 1);
        rs0 += __shfl_xor_sync(0xffffffffu, rs0, 2);
        rs1 += __shfl_xor_sync(0xffffffffu, rs1, 1);
        rs1 += __shfl_xor_sync(0xffffffffu, rs1, 2);
        l0 = l0 * a0 + rs0;
        l1 = l1 * a1 + rs1;

        // ---- O += P V (hi*hi + lo*hi + hi*lo) ----
#pragma unroll
        for (int js = 0; js < 4; js++) {
            uint32_t pah[4], pal[4];
            hl2(Sf[2*js][0],   Sf[2*js][1],   pah[0], pal[0]);
            hl2(Sf[2*js][2],   Sf[2*js][3],   pah[1], pal[1]);
            hl2(Sf[2*js+1][0], Sf[2*js+1][1], pah[2], pal[2]);
            hl2(Sf[2*js+1][2], Sf[2*js+1][3], pah[3], pal[3]);

            uint32_t Vhf[4][4], Vlf[4][4];
            const uint32_t voff = (uint32_t)(js * 16 + lrow) * (ATS * 2) + lhalf * 16;
#pragma unroll
            for (int dh = 0; dh < 4; dh++) {
                ldm4t(vha + voff + dh * 32, Vhf[dh]);
                ldm4t(vla + voff + dh * 32, Vlf[dh]);
            }
#pragma unroll
            for (int dt = 0; dt < 8; dt++) {
                const int dh = dt >> 1, o = (dt & 1) * 2;
                uint32_t b0h = Vhf[dh][o], b1h = Vhf[dh][o + 1];
                uint32_t b0l = Vlf[dh][o], b1l = Vlf[dh][o + 1];
                mma16816(O[dt], pah, b0h, b1h);
                mma16816(O[dt], pal, b0h, b1h);
                mma16816(O[dt], pah, b0l, b1l);
            }
        }
    }

    // epilogue: O /= l, hi/lo bf16 split, (b, l, (g h d)) layout
    float inv0 = 1.f / l0, inv1 = 1.f / l1;
#pragma unroll
    for (int dt = 0; dt < 8; dt++) {
        uint32_t h01, l01, h23, l23;
        hl2(O[dt][0] * inv0, O[dt][1] * inv0, h01, l01);
        hl2(O[dt][2] * inv1, O[dt][3] * inv1, h23, l23);
        size_t base0 = (size_t)(bb * LL + r0g) * DM + H * HD + dt * 8 + ecol;
        size_t base1 = (size_t)(bb * LL + r1g) * DM + H * HD + dt * 8 + ecol;
        *(uint32_t*)&o_hi[base0] = h01;
        *(uint32_t*)&o_lo[base0] = l01;
        *(uint32_t*)&o_hi[base1] = h23;
        *(uint32_t*)&o_lo[base1] = l23;
    }
}

// ---------------------------------------------------------------------------
extern "C" void kernel_launch(void* const* d_in, const int* in_sizes, int n_in,
                              void* d_out, int out_size)
{
    (void)in_sizes; (void)n_in; (void)out_size;
    const float* x    = (const float*)d_in[0];
    // d_in[1] (additive causal mask) reproduced exactly by in-kernel masking.
    const float* Wqkv = (const float*)d_in[2];
    const float* Wout = (const float*)d_in[3];
    float* out = (float*)d_out;

    __nv_bfloat16 *p_xh, *p_xl, *p_qh, *p_ql, *p_oh, *p_ol, *p_ohh, *p_oll;
    cudaGetSymbolAddress((void**)&p_xh, x_hi);
    cudaGetSymbolAddress((void**)&p_xl, x_lo);
    cudaGetSymbolAddress((void**)&p_qh, wq_hi);
    cudaGetSymbolAddress((void**)&p_ql, wq_lo);
    cudaGetSymbolAddress((void**)&p_oh, wo_hi);
    cudaGetSymbolAddress((void**)&p_ol, wo_lo);
    cudaGetSymbolAddress((void**)&p_ohh, o_hi);
    cudaGetSymbolAddress((void**)&p_oll, o_lo);

    // 0) prep: split/transposes
    split_x_kernel<<<(MTOT * DM / 4) / 256, 256>>>(x);
    wsplit_kernel<<<dim3(QKVN / 32, DM / 32), dim3(32, 8)>>>(Wqkv, p_qh, p_ql, DM, QKVN);
    wsplit_kernel<<<dim3(DM / 32, DM / 32), dim3(32, 8)>>>(Wout, p_oh, p_ol, DM, DM);

    // 1) QKV projection (HMMA), split into g_q/g_k/g_v
    hmma_gemm<1><<<dim3(QKVN / 128, MTOT / 128), 256>>>(p_xh, p_xl, p_qh, p_ql,
                                                        nullptr, QKVN);

    // 2) attention (HMMA flash)
    const int smbytes = (2 * 128 + 4 * 64) * ATS * (int)sizeof(__nv_bfloat16);
    cudaFuncSetAttribute(attn_kernel, cudaFuncAttributeMaxDynamicSharedMemorySize, smbytes);
    attn_kernel<<<dim3(LL / 128, BB * NH), 256, smbytes>>>();

    // 3) output projection (HMMA)
    hmma_gemm<0><<<dim3(DM / 128, MTOT / 128), 256>>>(p_ohh, p_oll, p_oh, p_ol,
                                                      out, DM);
}

// round 15
// speedup vs baseline: 1.9497x; 1.0049x over previous
#include <cuda_runtime.h>
#include <cuda_bf16.h>
#include <cstdint>

// Problem constants
#define BB   2
#define LL   2048
#define DM   2048
#define NH   32
#define NKV  8
#define HD   64
#define MTOT (BB*LL)      // 4096 rows (b*l)
#define KVW  (NKV*HD)     // 512
#define QKVN (DM + 2*KVW) // 3072

// fp32 scratch consumed by attention
__device__ __align__(256) float g_q[(size_t)MTOT*DM];
__device__ __align__(256) float g_k[(size_t)MTOT*KVW];
__device__ __align__(256) float g_v[(size_t)MTOT*KVW];
// bf16 hi/lo split operands for the tensor-core GEMMs
__device__ __align__(256) __nv_bfloat16 x_hi[(size_t)MTOT*DM];
__device__ __align__(256) __nv_bfloat16 x_lo[(size_t)MTOT*DM];
__device__ __align__(256) __nv_bfloat16 wq_hi[(size_t)QKVN*DM];  // [N=3072][K=2048] (transposed)
__device__ __align__(256) __nv_bfloat16 wq_lo[(size_t)QKVN*DM];
__device__ __align__(256) __nv_bfloat16 wo_hi[(size_t)DM*DM];    // [N=2048][K=2048]
__device__ __align__(256) __nv_bfloat16 wo_lo[(size_t)DM*DM];
__device__ __align__(256) __nv_bfloat16 o_hi[(size_t)MTOT*DM];   // attention out, split
__device__ __align__(256) __nv_bfloat16 o_lo[(size_t)MTOT*DM];

// ---------------------------------------------------------------------------
// Helpers
// ---------------------------------------------------------------------------
__device__ __forceinline__ uint32_t smem_u32(const void* p) {
    uint32_t a;
    asm("{ .reg .u64 t; cvta.to.shared.u64 t, %1; cvt.u32.u64 %0, t; }"
        : "=r"(a) : "l"(p));
    return a;
}

__device__ __forceinline__ void ldm4(uint32_t addr, uint32_t* r) {
    asm volatile("ldmatrix.sync.aligned.m8n8.x4.shared.b16 {%0,%1,%2,%3}, [%4];"
        : "=r"(r[0]), "=r"(r[1]), "=r"(r[2]), "=r"(r[3]) : "r"(addr));
}
__device__ __forceinline__ void ldm4t(uint32_t addr, uint32_t* r) {
    asm volatile("ldmatrix.sync.aligned.m8n8.x4.trans.shared.b16 {%0,%1,%2,%3}, [%4];"
        : "=r"(r[0]), "=r"(r[1]), "=r"(r[2]), "=r"(r[3]) : "r"(addr));
}

// D += A(m16k16) * B(n8k16)^T, bf16 in, fp32 accum
__device__ __forceinline__ void mma16816(float* c, const uint32_t* a,
                                         uint32_t b0, uint32_t b1) {
    asm volatile(
        "mma.sync.aligned.m16n8k16.row.col.f32.bf16.bf16.f32 "
        "{%0,%1,%2,%3}, {%4,%5,%6,%7}, {%8,%9}, {%0,%1,%2,%3};"
        : "+f"(c[0]), "+f"(c[1]), "+f"(c[2]), "+f"(c[3])
        : "r"(a[0]), "r"(a[1]), "r"(a[2]), "r"(a[3]), "r"(b0), "r"(b1));
}

__device__ __forceinline__ void cpasync16(uint32_t saddr, const void* gaddr) {
    asm volatile("cp.async.cg.shared.global [%0], [%1], 16;"
                 :: "r"(saddr), "l"(gaddr) : "memory");
}
#define CP_COMMIT() asm volatile("cp.async.commit_group;" ::: "memory")
#define CP_WAIT0()  asm volatile("cp.async.wait_group 0;" ::: "memory")

__device__ __forceinline__ void split_hl(float v, unsigned short& h, unsigned short& l) {
    __nv_bfloat16 bh = __float2bfloat16_rn(v);
    h = __bfloat16_as_ushort(bh);
    float r = v - __bfloat162float(bh);
    l = __bfloat16_as_ushort(__float2bfloat16_rn(r));
}

// two floats -> packed bf16x2 hi + residual bf16x2 lo
__device__ __forceinline__ void hl2(float f0, float f1, uint32_t& h, uint32_t& l) {
    unsigned short h0, l0, h1, l1;
    split_hl(f0, h0, l0);
    split_hl(f1, h1, l1);
    h = (uint32_t)h0 | ((uint32_t)h1 << 16);
    l = (uint32_t)l0 | ((uint32_t)l1 << 16);
}

// ---------------------------------------------------------------------------
// Prep kernels (unchanged, verified)
// ---------------------------------------------------------------------------
__global__ __launch_bounds__(256)
void split_x_kernel(const float* __restrict__ x)
{
    size_t i4 = (size_t)blockIdx.x * 256 + threadIdx.x;   // one float4 each
    float4 v = *((const float4*)x + i4);
    unsigned short h0, l0, h1, l1, h2, l2, h3, l3;
    split_hl(v.x, h0, l0); split_hl(v.y, h1, l1);
    split_hl(v.z, h2, l2); split_hl(v.w, h3, l3);
    *(uint2*)&x_hi[i4 * 4] = make_uint2((uint32_t)h0 | ((uint32_t)h1 << 16),
                                        (uint32_t)h2 | ((uint32_t)h3 << 16));
    *(uint2*)&x_lo[i4 * 4] = make_uint2((uint32_t)l0 | ((uint32_t)l1 << 16),
                                        (uint32_t)l2 | ((uint32_t)l3 << 16));
}

// Transpose W[K][N] -> T[N][K] with hi/lo split. block (32,8), 32x32 tiles.
__global__ __launch_bounds__(256)
void wsplit_kernel(const float* __restrict__ W, __nv_bfloat16* __restrict__ Thi,
                   __nv_bfloat16* __restrict__ Tlo, int K, int N)
{
    __shared__ float tile[32][33];
    int n0 = blockIdx.x * 32, k0 = blockIdx.y * 32;
    int tx = threadIdx.x, ty = threadIdx.y;
#pragma unroll
    for (int i = 0; i < 4; i++)
        tile[ty + 8 * i][tx] = W[(size_t)(k0 + ty + 8 * i) * N + n0 + tx];
    __syncthreads();
#pragma unroll
    for (int i = 0; i < 4; i++) {
        int n = n0 + ty + 8 * i, k = k0 + tx;
        unsigned short h, l;
        split_hl(tile[tx][ty + 8 * i], h, l);
        Thi[(size_t)n * K + k] = __ushort_as_bfloat16(h);
        Tlo[(size_t)n * K + k] = __ushort_as_bfloat16(l);
    }
}

// ---------------------------------------------------------------------------
// bf16x3 GEMM on mma.sync, cp.async 2-stage double buffering.
// C[128x128 tile] = A(hi+lo) @ B(hi+lo)^T, fp32 accum, dropping lo*lo.
// 8 warps in 2x4; warp tile 64x32.  One __syncthreads per k-chunk; global
// loads run on the async copy engine overlapped with the MMA phase.
// ---------------------------------------------------------------------------
#define KS 40             // halves per smem row (80B, 16B-aligned)
#define BK 32
#define NTCH (2048/BK)    // 64 k-chunks
#define ARRB (128*KS*2)   // bytes per operand array (10240)
#define STGB (4*ARRB)     // bytes per stage (40960)
#define GSMEM (2*STGB)    // total dynamic smem (81920)

template<int SPLIT>
__global__ __launch_bounds__(256)
void hmma_gemm(const __nv_bfloat16* __restrict__ Ahi, const __nv_bfloat16* __restrict__ Alo,
               const __nv_bfloat16* __restrict__ Bhi, const __nv_bfloat16* __restrict__ Blo,
               float* __restrict__ C, int N)
{
    extern __shared__ __nv_bfloat16 smd[];
    const uint32_t base = smem_u32(smd);

    const int t    = threadIdx.x;
    const int lane = t & 31, wid = t >> 5;
    const int wm = wid >> 2, wn = wid & 3;      // 2x4 warp grid
    const int m0 = blockIdx.y * 128;
    const int n0 = blockIdx.x * 128;

    const int lrow = lane & 15, lhalf = lane >> 4;

    uint32_t aOff[4], bOff[2];
#pragma unroll
    for (int mt = 0; mt < 4; mt++)
        aOff[mt] = (uint32_t)(wm * 64 + mt * 16 + lrow) * (KS * 2) + lhalf * 16;
#pragma unroll
    for (int np = 0; np < 2; np++)
        bOff[np] = (uint32_t)(wn * 32 + np * 16 + lrow) * (KS * 2) + lhalf * 16;

    const int grow = t >> 2, gq = t & 3;
    const __nv_bfloat16* srcs[4] = {
        Ahi + (size_t)m0 * 2048, Alo + (size_t)m0 * 2048,
        Bhi + (size_t)n0 * 2048, Blo + (size_t)n0 * 2048 };
    const uint32_t s0 = (uint32_t)(grow * KS + gq * 8) * 2;
    const uint32_t s1 = (uint32_t)((grow + 64) * KS + gq * 8) * 2;

    float acc[4][4][4];
#pragma unroll
    for (int mt = 0; mt < 4; mt++)
#pragma unroll
        for (int nt = 0; nt < 4; nt++)
#pragma unroll
            for (int r = 0; r < 4; r++) acc[mt][nt][r] = 0.f;

    // prologue: async-copy chunk 0 into stage 0
    {
        const uint32_t sb = base;
#pragma unroll
        for (int a = 0; a < 4; a++) {
            cpasync16(sb + a * ARRB + s0, srcs[a] + (size_t)grow * 2048 + gq * 8);
            cpasync16(sb + a * ARRB + s1, srcs[a] + (size_t)(grow + 64) * 2048 + gq * 8);
        }
        CP_COMMIT();
        CP_WAIT0();
        __syncthreads();
    }

    for (int c = 0; c < NTCH; c++) {
        // kick off chunk c+1 into the other stage (overlaps compute below)
        if (c + 1 < NTCH) {
            const int k0 = (c + 1) * BK;
            const uint32_t sb = base + ((c + 1) & 1) * STGB;
#pragma unroll
            for (int a = 0; a < 4; a++) {
                cpasync16(sb + a * ARRB + s0, srcs[a] + (size_t)grow * 2048 + k0 + gq * 8);
                cpasync16(sb + a * ARRB + s1, srcs[a] + (size_t)(grow + 64) * 2048 + k0 + gq * 8);
            }
            CP_COMMIT();
        }

        // compute chunk c from its stage
        const uint32_t sb = base + (c & 1) * STGB;
        const uint32_t smb0 = sb, smb1 = sb + ARRB, smb2 = sb + 2 * ARRB, smb3 = sb + 3 * ARRB;
#pragma unroll
        for (int ks = 0; ks < 2; ks++) {
            const uint32_t kb = ks * 32;
            uint32_t Af[4][4], Bf[2][4], Cf[2][4];
#pragma unroll
            for (int mt = 0; mt < 4; mt++) ldm4(smb0 + aOff[mt] + kb, Af[mt]);
#pragma unroll
            for (int np = 0; np < 2; np++) ldm4(smb2 + bOff[np] + kb, Bf[np]);
#pragma unroll
            for (int mt = 0; mt < 4; mt++)
#pragma unroll
                for (int nt = 0; nt < 4; nt++)
                    mma16816(acc[mt][nt], Af[mt],
                             Bf[nt >> 1][nt & 1], Bf[nt >> 1][2 + (nt & 1)]);
#pragma unroll
            for (int np = 0; np < 2; np++) ldm4(smb3 + bOff[np] + kb, Cf[np]);
#pragma unroll
            for (int mt = 0; mt < 4; mt++)
#pragma unroll
                for (int nt = 0; nt < 4; nt++)
                    mma16816(acc[mt][nt], Af[mt],
                             Cf[nt >> 1][nt & 1], Cf[nt >> 1][2 + (nt & 1)]);
#pragma unroll
            for (int mt = 0; mt < 4; mt++) ldm4(smb1 + aOff[mt] + kb, Af[mt]);
#pragma unroll
            for (int mt = 0; mt < 4; mt++)
#pragma unroll
                for (int nt = 0; nt < 4; nt++)
                    mma16816(acc[mt][nt], Af[mt],
                             Bf[nt >> 1][nt & 1], Bf[nt >> 1][2 + (nt & 1)]);
        }

        if (c + 1 < NTCH) {
            CP_WAIT0();          // chunk c+1 copy done (ran during compute)
            __syncthreads();     // also protects stage reuse two iters later
        }
    }

    float* dst; int ldd, cb;
    if (SPLIT == 0)               { dst = C;   ldd = N;   cb = n0; }
    else if (n0 < NH * HD)        { dst = g_q; ldd = DM;  cb = n0; }
    else if (n0 < (NH+NKV) * HD)  { dst = g_k; ldd = KVW; cb = n0 - NH*HD; }
    else                          { dst = g_v; ldd = KVW; cb = n0 - (NH+NKV)*HD; }

    const int erow = lane >> 2, ecol = (lane & 3) * 2;
#pragma unroll
    for (int mt = 0; mt < 4; mt++) {
        const int r0 = m0 + wm * 64 + mt * 16 + erow;
#pragma unroll
        for (int nt = 0; nt < 4; nt++) {
            const int cc = cb + wn * 32 + nt * 8 + ecol;
            *(float2*)&dst[(size_t)r0 * ldd + cc]       =
                make_float2(acc[mt][nt][0], acc[mt][nt][1]);
            *(float2*)&dst[(size_t)(r0 + 8) * ldd + cc] =
                make_float2(acc[mt][nt][2], acc[mt][nt][3]);
        }
    }
}

// ---------------------------------------------------------------------------
// Flash attention on HMMA (bf16 hi/lo x3) — verified in R13, unchanged.
// ---------------------------------------------------------------------------
#define ATS 72   // bf16 halves per smem row (144B; rows stagger 16B in banks)

__global__ __launch_bounds__(256)
void attn_kernel()
{
    extern __shared__ __nv_bfloat16 smb[];
    __nv_bfloat16* Qh = smb;                 // [128][ATS]
    __nv_bfloat16* Ql = Qh + 128 * ATS;
    __nv_bfloat16* Kh = Ql + 128 * ATS;      // [64][ATS]
    __nv_bfloat16* Kl = Kh + 64 * ATS;
    __nv_bfloat16* Vh = Kl + 64 * ATS;
    __nv_bfloat16* Vl = Vh + 64 * ATS;

    const int t = threadIdx.x;
    const int lane = t & 31, w = t >> 5;
    const int lrow = lane & 15, lhalf = lane >> 4;
    const int erow = lane >> 2, ecol = (lane & 3) * 2;

    const int qb = (int)gridDim.x - 1 - (int)blockIdx.x;  // big blocks first
    const int bH = blockIdx.y;
    const int bb = bH >> 5;
    const int H  = bH & 31;
    const int hk = H & 7;
    const int qg0 = qb * 128;

    const float* Qg = g_q + (size_t)bb * LL * DM  + (size_t)H  * LL * HD;
    const float* Kg = g_k + (size_t)bb * LL * KVW + (size_t)hk * LL * HD;
    const float* Vg = g_v + (size_t)bb * LL * KVW + (size_t)hk * LL * HD;

    // fill Q smem (hi/lo): 128x64 fp32 -> 32 floats per thread
#pragma unroll
    for (int s = 0; s < 8; s++) {
        int idx = t + 256 * s;                 // 0..2047 float4s
        int row = idx >> 4, d4 = (idx & 15) << 2;
        float4 v = *(const float4*)&Qg[(size_t)(qg0 + row) * HD + d4];
        unsigned short h0,l0,h1,l1,h2,l2,h3,l3;
        split_hl(v.x, h0, l0); split_hl(v.y, h1, l1);
        split_hl(v.z, h2, l2); split_hl(v.w, h3, l3);
        *(uint2*)&Qh[row * ATS + d4] = make_uint2((uint32_t)h0 | ((uint32_t)h1 << 16),
                                                  (uint32_t)h2 | ((uint32_t)h3 << 16));
        *(uint2*)&Ql[row * ATS + d4] = make_uint2((uint32_t)l0 | ((uint32_t)l1 << 16),
                                                  (uint32_t)l2 | ((uint32_t)l3 << 16));
    }
    __syncthreads();

    // Q fragments (held in regs for the whole kernel)
    uint32_t Qf[2][4][4];
    {
        uint32_t qoff = (uint32_t)(w * 16 + lrow) * (ATS * 2) + lhalf * 16;
        uint32_t qha = smem_u32(Qh), qla = smem_u32(Ql);
#pragma unroll
        for (int ks = 0; ks < 4; ks++) {
            ldm4(qha + qoff + ks * 32, Qf[0][ks]);
            ldm4(qla + qoff + ks * 32, Qf[1][ks]);
        }
    }

    const uint32_t kha = smem_u32(Kh), kla = smem_u32(Kl);
    const uint32_t vha = smem_u32(Vh), vla = smem_u32(Vl);
    const uint32_t koff = (uint32_t)lrow * (ATS * 2) + lhalf * 16;

    float m0 = -1e30f, m1 = -1e30f, l0 = 0.f, l1 = 0.f;
    float O[8][4];
#pragma unroll
    for (int dt = 0; dt < 8; dt++)
#pragma unroll
        for (int r = 0; r < 4; r++) O[dt][r] = 0.f;

    const int wrow = qg0 + w * 16;          // warp's first row
    const int r0g = wrow + erow;            // this lane's rows
    const int r1g = r0g + 8;
    const int nkb = 2 * qb + 2;

    for (int kb = 0; kb < nkb; kb++) {
        const int j0 = kb * 64;
        __syncthreads();
        // fill K,V hi/lo: 64x64 fp32 each -> 4 float4 per thread per tensor
#pragma unroll
        for (int s = 0; s < 4; s++) {
            int idx = t + 256 * s;
            int row = idx >> 4, d4 = (idx & 15) << 2;
            float4 kv = *(const float4*)&Kg[(size_t)(j0 + row) * HD + d4];
            unsigned short h0,lw0,h1,lw1,h2,lw2,h3,lw3;
            split_hl(kv.x, h0, lw0); split_hl(kv.y, h1, lw1);
            split_hl(kv.z, h2, lw2); split_hl(kv.w, h3, lw3);
            *(uint2*)&Kh[row * ATS + d4] = make_uint2((uint32_t)h0 | ((uint32_t)h1 << 16),
                                                      (uint32_t)h2 | ((uint32_t)h3 << 16));
            *(uint2*)&Kl[row * ATS + d4] = make_uint2((uint32_t)lw0 | ((uint32_t)lw1 << 16),
                                                      (uint32_t)lw2 | ((uint32_t)lw3 << 16));
            float4 vv = *(const float4*)&Vg[(size_t)(j0 + row) * HD + d4];
            split_hl(vv.x, h0, lw0); split_hl(vv.y, h1, lw1);
            split_hl(vv.z, h2, lw2); split_hl(vv.w, h3, lw3);
            *(uint2*)&Vh[row * ATS + d4] = make_uint2((uint32_t)h0 | ((uint32_t)h1 << 16),
                                                      (uint32_t)h2 | ((uint32_t)h3 << 16));
            *(uint2*)&Vl[row * ATS + d4] = make_uint2((uint32_t)lw0 | ((uint32_t)lw1 << 16),
                                                      (uint32_t)lw2 | ((uint32_t)lw3 << 16));
        }
        __syncthreads();

        if (j0 > wrow + 15) continue;       // fully masked for this warp
        const bool pmask = (j0 + 63 > wrow);

        // ---- S = Q K^T (hi*hi + lo*hi + hi*lo) ----
        float Sf[8][4];
#pragma unroll
        for (int nt = 0; nt < 8; nt++)
#pragma unroll
            for (int r = 0; r < 4; r++) Sf[nt][r] = 0.f;

#pragma unroll
        for (int ks = 0; ks < 4; ks++) {
            uint32_t Khf[4][4], Klf[4][4];
#pragma unroll
            for (int g = 0; g < 4; g++) {
                ldm4(kha + (uint32_t)g * 16 * (ATS * 2) + koff + ks * 32, Khf[g]);
                ldm4(kla + (uint32_t)g * 16 * (ATS * 2) + koff + ks * 32, Klf[g]);
            }
#pragma unroll
            for (int nt = 0; nt < 8; nt++) {
                uint32_t b0h = Khf[nt >> 1][nt & 1], b1h = Khf[nt >> 1][2 + (nt & 1)];
                uint32_t b0l = Klf[nt >> 1][nt & 1], b1l = Klf[nt >> 1][2 + (nt & 1)];
                mma16816(Sf[nt], Qf[0][ks], b0h, b1h);
                mma16816(Sf[nt], Qf[1][ks], b0h, b1h);
                mma16816(Sf[nt], Qf[0][ks], b0l, b1l);
            }
        }

        // ---- online softmax in fragment space ----
        float mx0 = -1e30f, mx1 = -1e30f;
#pragma unroll
        for (int nt = 0; nt < 8; nt++) {
#pragma unroll
            for (int v = 0; v < 2; v++) {
                float s = Sf[nt][v] * 0.125f;
                if (pmask && (j0 + nt * 8 + ecol + v > r0g)) s = -1e30f;
                Sf[nt][v] = s;
                mx0 = fmaxf(mx0, s);
            }
#pragma unroll
            for (int v = 2; v < 4; v++) {
                float s = Sf[nt][v] * 0.125f;
                if (pmask && (j0 + nt * 8 + ecol + v - 2 > r1g)) s = -1e30f;
                Sf[nt][v] = s;
                mx1 = fmaxf(mx1, s);
            }
        }
        mx0 = fmaxf(mx0, __shfl_xor_sync(0xffffffffu, mx0, 1));
        mx0 = fmaxf(mx0, __shfl_xor_sync(0xffffffffu, mx0, 2));
        mx1 = fmaxf(mx1, __shfl_xor_sync(0xffffffffu, mx1, 1));
        mx1 = fmaxf(mx1, __shfl_xor_sync(0xffffffffu, mx1, 2));

        float mn0 = fmaxf(m0, mx0), mn1 = fmaxf(m1, mx1);
        float a0 = __expf(m0 - mn0), a1 = __expf(m1 - mn1);
        m0 = mn0; m1 = mn1;
#pragma unroll
        for (int dt = 0; dt < 8; dt++) {
            O[dt][0] *= a0; O[dt][1] *= a0;
            O[dt][2] *= a1; O[dt][3] *= a1;
        }
        float rs0 = 0.f, rs1 = 0.f;
#pragma unroll
        for (int nt = 0; nt < 8; nt++) {
#pragma unroll
            for (int v = 0; v < 2; v++) {
                float p = __expf(Sf[nt][v] - mn0);
                Sf[nt][v] = p; rs0 += p;
            }
#pragma unroll
            for (int v = 2; v < 4; v++) {
                float p = __expf(Sf[nt][v] - mn1);
                Sf[nt][v] = p; rs1 += p;
            }
        }
        rs0 += __shfl_xor_sync(0xffffffffu, rs0, 1);
        rs0 += __shfl_xor_sync(0xffffffffu, rs0, 2);
        rs1 += __shfl_xor_sync(0xffffffffu, rs1, 1);
        rs1 += __shfl_xor_sync(0xffffffffu, rs1, 2);
        l0 = l0 * a0 + rs0;
        l1 = l1 * a1 + rs1;

        // ---- O += P V (hi*hi + lo*hi + hi*lo) ----
#pragma unroll
        for (int js = 0; js < 4; js++) {
            uint32_t pah[4], pal[4];
            hl2(Sf[2*js][0],   Sf[2*js][1],   pah[0], pal[0]);
            hl2(Sf[2*js][2],   Sf[2*js][3],   pah[1], pal[1]);
            hl2(Sf[2*js+1][0], Sf[2*js+1][1], pah[2], pal[2]);
            hl2(Sf[2*js+1][2], Sf[2*js+1][3], pah[3], pal[3]);

            uint32_t Vhf[4][4], Vlf[4][4];
            const uint32_t voff = (uint32_t)(js * 16 + lrow) * (ATS * 2) + lhalf * 16;
#pragma unroll
            for (int dh = 0; dh < 4; dh++) {
                ldm4t(vha + voff + dh * 32, Vhf[dh]);
                ldm4t(vla + voff + dh * 32, Vlf[dh]);
            }
#pragma unroll
            for (int dt = 0; dt < 8; dt++) {
                const int dh = dt >> 1, o = (dt & 1) * 2;
                uint32_t b0h = Vhf[dh][o], b1h = Vhf[dh][o + 1];
                uint32_t b0l = Vlf[dh][o], b1l = Vlf[dh][o + 1];
                mma16816(O[dt], pah, b0h, b1h);
                mma16816(O[dt], pal, b0h, b1h);
                mma16816(O[dt], pah, b0l, b1l);
            }
        }
    }

    // epilogue: O /= l, hi/lo bf16 split, (b, l, (g h d)) layout
    float inv0 = 1.f / l0, inv1 = 1.f / l1;
#pragma unroll
    for (int dt = 0; dt < 8; dt++) {
        uint32_t h01, l01, h23, l23;
        hl2(O[dt][0] * inv0, O[dt][1] * inv0, h01, l01);
        hl2(O[dt][2] * inv1, O[dt][3] * inv1, h23, l23);
        size_t base0 = (size_t)(bb * LL + r0g) * DM + H * HD + dt * 8 + ecol;
        size_t base1 = (size_t)(bb * LL + r1g) * DM + H * HD + dt * 8 + ecol;
        *(uint32_t*)&o_hi[base0] = h01;
        *(uint32_t*)&o_lo[base0] = l01;
        *(uint32_t*)&o_hi[base1] = h23;
        *(uint32_t*)&o_lo[base1] = l23;
    }
}

// ---------------------------------------------------------------------------
extern "C" void kernel_launch(void* const* d_in, const int* in_sizes, int n_in,
                              void* d_out, int out_size)
{
    (void)in_sizes; (void)n_in; (void)out_size;
    const float* x    = (const float*)d_in[0];
    // d_in[1] (additive causal mask) reproduced exactly by in-kernel masking.
    const float* Wqkv = (const float*)d_in[2];
    const float* Wout = (const float*)d_in[3];
    float* out = (float*)d_out;

    __nv_bfloat16 *p_xh, *p_xl, *p_qh, *p_ql, *p_oh, *p_ol, *p_ohh, *p_oll;
    cudaGetSymbolAddress((void**)&p_xh, x_hi);
    cudaGetSymbolAddress((void**)&p_xl, x_lo);
    cudaGetSymbolAddress((void**)&p_qh, wq_hi);
    cudaGetSymbolAddress((void**)&p_ql, wq_lo);
    cudaGetSymbolAddress((void**)&p_oh, wo_hi);
    cudaGetSymbolAddress((void**)&p_ol, wo_lo);
    cudaGetSymbolAddress((void**)&p_ohh, o_hi);
    cudaGetSymbolAddress((void**)&p_oll, o_lo);

    cudaFuncSetAttribute(hmma_gemm<1>, cudaFuncAttributeMaxDynamicSharedMemorySize, GSMEM);
    cudaFuncSetAttribute(hmma_gemm<0>, cudaFuncAttributeMaxDynamicSharedMemorySize, GSMEM);

    // 0) prep: split/transposes
    split_x_kernel<<<(MTOT * DM / 4) / 256, 256>>>(x);
    wsplit_kernel<<<dim3(QKVN / 32, DM / 32), dim3(32, 8)>>>(Wqkv, p_qh, p_ql, DM, QKVN);
    wsplit_kernel<<<dim3(DM / 32, DM / 32), dim3(32, 8)>>>(Wout, p_oh, p_ol, DM, DM);

    // 1) QKV projection (HMMA + cp.async), split into g_q/g_k/g_v
    hmma_gemm<1><<<dim3(QKVN / 128, MTOT / 128), 256, GSMEM>>>(p_xh, p_xl, p_qh, p_ql,
                                                               nullptr, QKVN);

    // 2) attention (HMMA flash)
    const int smbytes = (2 * 128 + 4 * 64) * ATS * (int)sizeof(__nv_bfloat16);
    cudaFuncSetAttribute(attn_kernel, cudaFuncAttributeMaxDynamicSharedMemorySize, smbytes);
    attn_kernel<<<dim3(LL / 128, BB * NH), 256, smbytes>>>();

    // 3) output projection (HMMA + cp.async)
    hmma_gemm<0><<<dim3(DM / 128, MTOT / 128), 256, GSMEM>>>(p_ohh, p_oll, p_oh, p_ol,
                                                             out, DM);
}